// round 1
// baseline (speedup 1.0000x reference)
#include <cuda_runtime.h>
#include <math.h>

#define Bc   2
#define Tc   1024
#define Dc   1024
#define Hc   16
#define DHc  64
#define DFFc 4096
#define Vc   32000
#define WINc 3
#define Rc   8
#define VTc  (Vc/128)      // 250 vocab tiles
#define NR   (Bc*Tc)       // 2048 rows

#define GF_ADD  1
#define GF_GELU 2

// ---------------- device scratch (no allocations allowed) ----------------
__device__ float g_Wqkv_eff[Dc*3*Dc];
__device__ float g_Wo_eff[Dc*Dc];
__device__ float g_E   [NR*Dc];      // token embeddings (mutable latent slots)
__device__ float g_X   [NR*Dc];      // residual stream
__device__ float g_A   [NR*Dc];      // LN outputs / GEMM input
__device__ float g_QKV [NR*3*Dc];    // doubles as KV cache
__device__ float g_CTX [NR*Dc];
__device__ float g_G   [NR*DFFc];
__device__ float g_HID [NR*Dc];      // final-LN hidden states
__device__ float g_partM[NR*VTc];
__device__ float g_partS[NR*VTc];
__device__ float g_labelLogit[NR];
__device__ float g_nll[NR];

// ---------------- helpers ----------------
__device__ __forceinline__ float blockReduceSum(float v, float* sh) {
    int tid = threadIdx.x;
    #pragma unroll
    for (int o = 16; o > 0; o >>= 1) v += __shfl_xor_sync(0xffffffffu, v, o);
    if ((tid & 31) == 0) sh[tid >> 5] = v;
    __syncthreads();
    if (tid < 32) {
        float x = (tid < (int)(blockDim.x >> 5)) ? sh[tid] : 0.f;
        #pragma unroll
        for (int o = 16; o > 0; o >>= 1) x += __shfl_xor_sync(0xffffffffu, x, o);
        if (tid == 0) sh[0] = x;
    }
    __syncthreads();
    float r = sh[0];
    __syncthreads();
    return r;
}

__device__ __forceinline__ float gelu_tanh(float x) {
    float x3 = x * x * x;
    return 0.5f * x * (1.f + tanhf(0.7978845608028654f * (x + 0.044715f * x3)));
}

// ---------------- weight merge: W + 2*(A@B) ----------------
__global__ void k_effqkv(const float* __restrict__ W, const float* __restrict__ Aq,
                         const float* __restrict__ Bq) {
    int i = blockIdx.x * 256 + threadIdx.x;
    if (i >= Dc * 3 * Dc) return;
    int d = i / (3 * Dc), j = i % (3 * Dc);
    float acc = 0.f;
    #pragma unroll
    for (int r = 0; r < Rc; r++) acc += Aq[d * Rc + r] * Bq[r * 3 * Dc + j];
    g_Wqkv_eff[i] = W[i] + 2.0f * acc;   // sc = ALPHA/R = 2
}

__global__ void k_effo(const float* __restrict__ W, const float* __restrict__ Ao,
                       const float* __restrict__ Bo) {
    int i = blockIdx.x * 256 + threadIdx.x;
    if (i >= Dc * Dc) return;
    int d = i / Dc, j = i % Dc;
    float acc = 0.f;
    #pragma unroll
    for (int r = 0; r < Rc; r++) acc += Ao[d * Rc + r] * Bo[r * Dc + j];
    g_Wo_eff[i] = W[i] + 2.0f * acc;
}

// ---------------- embedding lookup ----------------
__global__ void k_embed(const int* __restrict__ ids, const float* __restrict__ emb) {
    int i = blockIdx.x * 256 + threadIdx.x;
    if (i >= NR * Dc) return;
    int rid = i / Dc, d = i % Dc;
    g_E[i] = emb[(size_t)ids[rid] * Dc + d];
}

// ---------------- LN kernels (two-pass mean/var; D=1024, 256 threads) ----------------
__global__ void k_ln1(const float* __restrict__ Wpos, const float* __restrict__ s,
                      const float* __restrict__ bb, int t0, int len) {
    __shared__ float sh[32];
    int r = blockIdx.x;
    int b = r / len, t = t0 + (r - b * len);
    size_t rid = (size_t)b * Tc + t;
    int tid = threadIdx.x;
    float v[4]; float sum = 0.f;
    #pragma unroll
    for (int i = 0; i < 4; i++) {
        int d = tid + i * 256;
        float x = g_E[rid * Dc + d] + Wpos[(size_t)t * Dc + d];
        v[i] = x; sum += x;
    }
    sum = blockReduceSum(sum, sh);
    float mean = sum * (1.f / Dc);
    float sq = 0.f;
    #pragma unroll
    for (int i = 0; i < 4; i++) { float dd = v[i] - mean; sq += dd * dd; }
    sq = blockReduceSum(sq, sh);
    float inv = rsqrtf(sq * (1.f / Dc) + 1e-5f);
    #pragma unroll
    for (int i = 0; i < 4; i++) {
        int d = tid + i * 256;
        g_X[rid * Dc + d] = v[i];
        g_A[rid * Dc + d] = (v[i] - mean) * inv * s[d] + bb[d];
    }
}

__global__ void k_lng(const float* __restrict__ in, const float* __restrict__ s,
                      const float* __restrict__ bb, float* __restrict__ out,
                      int t0, int len) {
    __shared__ float sh[32];
    int r = blockIdx.x;
    int b = r / len, t = t0 + (r - b * len);
    size_t rid = (size_t)b * Tc + t;
    int tid = threadIdx.x;
    float v[4]; float sum = 0.f;
    #pragma unroll
    for (int i = 0; i < 4; i++) {
        float x = in[rid * Dc + tid + i * 256];
        v[i] = x; sum += x;
    }
    sum = blockReduceSum(sum, sh);
    float mean = sum * (1.f / Dc);
    float sq = 0.f;
    #pragma unroll
    for (int i = 0; i < 4; i++) { float dd = v[i] - mean; sq += dd * dd; }
    sq = blockReduceSum(sq, sh);
    float inv = rsqrtf(sq * (1.f / Dc) + 1e-5f);
    #pragma unroll
    for (int i = 0; i < 4; i++) {
        int d = tid + i * 256;
        out[rid * Dc + d] = (v[i] - mean) * inv * s[d] + bb[d];
    }
}

// ---------------- generic fp32 GEMM: C[rows,N] (+)= act(A[rows,K] @ B[K,N] + bias) ----------------
// rows map r -> rid = b*Tc + t0 + (r - b*len),  M = 2*len.  128x128 tile, 8x8 microtile.
__global__ __launch_bounds__(256, 2) void k_gemm(
    const float* __restrict__ A, const float* __restrict__ Bm,
    const float* __restrict__ bias, float* __restrict__ C,
    int t0, int len, int K, int N, int flags)
{
    __shared__ float as[8][128];
    __shared__ float bs[8][128];
    int M = 2 * len;
    int tid = threadIdx.x;
    int tx = tid & 15, ty = tid >> 4;
    int bcol = blockIdx.x * 128, brow = blockIdx.y * 128;
    float acc[8][8];
    #pragma unroll
    for (int i = 0; i < 8; i++)
        #pragma unroll
        for (int j = 0; j < 8; j++) acc[i][j] = 0.f;

    int lr = tid >> 1, lk = (tid & 1) * 4;
    int bk = tid >> 5, bc = (tid & 31) * 4;
    const float* Arow = nullptr;
    int r0 = brow + lr;
    if (r0 < M) {
        int b = r0 / len;
        size_t rid = (size_t)b * Tc + t0 + (r0 - b * len);
        Arow = A + rid * (size_t)K;
    }
    const float* Bp = Bm + (size_t)bk * N + bcol + bc;

    for (int k0 = 0; k0 < K; k0 += 8) {
        float4 av = Arow ? *(const float4*)(Arow + k0 + lk) : make_float4(0.f, 0.f, 0.f, 0.f);
        float4 bv = *(const float4*)(Bp + (size_t)k0 * N);
        as[lk + 0][lr] = av.x; as[lk + 1][lr] = av.y;
        as[lk + 2][lr] = av.z; as[lk + 3][lr] = av.w;
        *(float4*)&bs[bk][bc] = bv;
        __syncthreads();
        #pragma unroll
        for (int k = 0; k < 8; k++) {
            float a[8], bb2[8];
            *(float4*)(a)     = *(const float4*)&as[k][ty * 8];
            *(float4*)(a + 4) = *(const float4*)&as[k][ty * 8 + 4];
            *(float4*)(bb2)     = *(const float4*)&bs[k][tx * 8];
            *(float4*)(bb2 + 4) = *(const float4*)&bs[k][tx * 8 + 4];
            #pragma unroll
            for (int i = 0; i < 8; i++)
                #pragma unroll
                for (int j = 0; j < 8; j++) acc[i][j] += a[i] * bb2[j];
        }
        __syncthreads();
    }

    #pragma unroll
    for (int i = 0; i < 8; i++) {
        int r = brow + ty * 8 + i;
        if (r >= M) continue;
        int b = r / len;
        size_t rid = (size_t)b * Tc + t0 + (r - b * len);
        float* Crow = C + rid * (size_t)N + bcol + tx * 8;
        #pragma unroll
        for (int j = 0; j < 8; j++) {
            float vv = acc[i][j] + bias[bcol + tx * 8 + j];
            if (flags & GF_GELU) vv = gelu_tanh(vv);
            if (flags & GF_ADD)  vv += Crow[j];
            Crow[j] = vv;
        }
    }
}

// ---------------- attention: one warp per query, online softmax over KV cache ----------------
__global__ void k_attn(int t0, int len) {
    int warp = threadIdx.x >> 5, lane = threadIdx.x & 31;
    int t = t0 + blockIdx.x * 4 + warp;
    if (t >= t0 + len) return;
    int h = blockIdx.y, b = blockIdx.z;
    const float* qp = g_QKV + ((size_t)(b * Tc + t) * 3 * Dc) + h * DHc;
    float2 q = *(const float2*)(qp + lane * 2);
    float m = -1e30f, l = 0.f, a0 = 0.f, a1 = 0.f;
    for (int s = 0; s <= t; s++) {
        const float* kp = g_QKV + ((size_t)(b * Tc + s) * 3 * Dc) + Dc + h * DHc;
        float2 kv = *(const float2*)(kp + lane * 2);
        float p = q.x * kv.x + q.y * kv.y;
        #pragma unroll
        for (int o = 16; o > 0; o >>= 1) p += __shfl_xor_sync(0xffffffffu, p, o);
        p *= 0.125f;                                   // 1/sqrt(64)
        float mn = fmaxf(m, p);
        float corr = expf(m - mn);
        float w = expf(p - mn);
        l = l * corr + w;
        float2 vv = *(const float2*)(kp + Dc + lane * 2);
        a0 = a0 * corr + w * vv.x;
        a1 = a1 * corr + w * vv.y;
        m = mn;
    }
    float invl = 1.f / l;
    float* cp = g_CTX + ((size_t)(b * Tc + t) * Dc) + h * DHc;
    ((float2*)cp)[lane] = make_float2(a0 * invl, a1 * invl);
}

// ---------------- latent scatter: E[b,tok] = softmax(latent_w[WIN-n:]) . HID[b,tok-n:tok] ----------------
__global__ void k_latent(const float* __restrict__ latw, int tok, int n) {
    int b = blockIdx.y;
    int d = blockIdx.x * 256 + threadIdx.x;
    if (d >= Dc) return;
    float w[WINc]; float mx = -1e30f;
    for (int i = 0; i < n; i++) { w[i] = latw[WINc - n + i]; mx = fmaxf(mx, w[i]); }
    float ssum = 0.f;
    for (int i = 0; i < n; i++) { w[i] = expf(w[i] - mx); ssum += w[i]; }
    float acc = 0.f;
    for (int i = 0; i < n; i++)
        acc += (w[i] / ssum) * g_HID[(size_t)(b * Tc + tok - n + i) * Dc + d];
    g_E[(size_t)(b * Tc + tok) * Dc + d] = acc;
}

// ---------------- lm_head fused with log-softmax partials + label-logit capture ----------------
__global__ __launch_bounds__(256, 2) void k_lmh(const float* __restrict__ emb,
                                                const int* __restrict__ labels) {
    __shared__ float as[8][128];
    __shared__ float es[8][128];
    __shared__ float smM[128][16];
    __shared__ float smS[128][16];
    int tid = threadIdx.x;
    int tx = tid & 15, ty = tid >> 4;
    int vb = blockIdx.x * 128, rb = blockIdx.y * 128;
    float acc[8][8];
    #pragma unroll
    for (int i = 0; i < 8; i++)
        #pragma unroll
        for (int j = 0; j < 8; j++) acc[i][j] = 0.f;

    int lr = tid >> 1, lk = (tid & 1) * 4;
    const float* Arow = g_HID + (size_t)(rb + lr) * Dc;
    const float* Erow = emb + (size_t)(vb + lr) * Dc;

    for (int k0 = 0; k0 < Dc; k0 += 8) {
        float4 av = *(const float4*)(Arow + k0 + lk);
        float4 ev = *(const float4*)(Erow + k0 + lk);
        as[lk + 0][lr] = av.x; as[lk + 1][lr] = av.y;
        as[lk + 2][lr] = av.z; as[lk + 3][lr] = av.w;
        es[lk + 0][lr] = ev.x; es[lk + 1][lr] = ev.y;
        es[lk + 2][lr] = ev.z; es[lk + 3][lr] = ev.w;
        __syncthreads();
        #pragma unroll
        for (int k = 0; k < 8; k++) {
            float a[8], e[8];
            *(float4*)(a)     = *(const float4*)&as[k][ty * 8];
            *(float4*)(a + 4) = *(const float4*)&as[k][ty * 8 + 4];
            *(float4*)(e)     = *(const float4*)&es[k][tx * 8];
            *(float4*)(e + 4) = *(const float4*)&es[k][tx * 8 + 4];
            #pragma unroll
            for (int i = 0; i < 8; i++)
                #pragma unroll
                for (int j = 0; j < 8; j++) acc[i][j] += a[i] * e[j];
        }
        __syncthreads();
    }

    // per-thread local (max, sumexp) over its 8 vocab cols, per row
    #pragma unroll
    for (int i = 0; i < 8; i++) {
        float lm = -1e30f;
        #pragma unroll
        for (int j = 0; j < 8; j++) lm = fmaxf(lm, acc[i][j]);
        float ls = 0.f;
        #pragma unroll
        for (int j = 0; j < 8; j++) ls += expf(acc[i][j] - lm);
        smM[ty * 8 + i][tx] = lm;
        smS[ty * 8 + i][tx] = ls;
    }
    __syncthreads();
    if (tid < 128) {
        float M = -1e30f;
        #pragma unroll
        for (int j = 0; j < 16; j++) M = fmaxf(M, smM[tid][j]);
        float S = 0.f;
        #pragma unroll
        for (int j = 0; j < 16; j++) S += smS[tid][j] * expf(smM[tid][j] - M);
        int rid = rb + tid;
        g_partM[(size_t)rid * VTc + blockIdx.x] = M;
        g_partS[(size_t)rid * VTc + blockIdx.x] = S;
    }
    // capture label logit
    #pragma unroll
    for (int i = 0; i < 8; i++) {
        int rid = rb + ty * 8 + i;
        int b = rid / Tc, t = rid % Tc;
        if (t < Tc - 1) {
            int lab = labels[b * Tc + t + 1];
            int rel = lab - (vb + tx * 8);
            if (rel >= 0 && rel < 8) g_labelLogit[rid] = acc[i][rel];
        }
    }
}

__global__ void k_lse(void) {
    __shared__ float sm[128];
    int row = blockIdx.x;
    int t = row % Tc;
    int tid = threadIdx.x;
    if (t == Tc - 1) { if (tid == 0) g_nll[row] = 0.f; return; }
    float M = -1e30f;
    for (int i = tid; i < VTc; i += 128) M = fmaxf(M, g_partM[(size_t)row * VTc + i]);
    sm[tid] = M; __syncthreads();
    for (int s = 64; s > 0; s >>= 1) { if (tid < s) sm[tid] = fmaxf(sm[tid], sm[tid + s]); __syncthreads(); }
    M = sm[0]; __syncthreads();
    float S = 0.f;
    for (int i = tid; i < VTc; i += 128)
        S += g_partS[(size_t)row * VTc + i] * expf(g_partM[(size_t)row * VTc + i] - M);
    sm[tid] = S; __syncthreads();
    for (int s = 64; s > 0; s >>= 1) { if (tid < s) sm[tid] += sm[tid + s]; __syncthreads(); }
    if (tid == 0) g_nll[row] = M + logf(sm[0]) - g_labelLogit[row];
}

__global__ void k_final(float* out) {
    __shared__ float sh[32];
    float s = 0.f;
    for (int i = threadIdx.x; i < NR; i += 256) s += g_nll[i];
    s = blockReduceSum(s, sh);
    if (threadIdx.x == 0) out[0] = s / (float)(Bc * (Tc - 1));
}

// ---------------- host orchestration ----------------
extern "C" void kernel_launch(void* const* d_in, const int* in_sizes, int n_in,
                              void* d_out, int out_size) {
    const int*   ids    = (const int*)d_in[0];
    const int*   labels = (const int*)d_in[2];
    const float* emb    = (const float*)d_in[4];
    const float* Wpos   = (const float*)d_in[5];
    const float* Wqkv   = (const float*)d_in[6];
    const float* bqkv   = (const float*)d_in[7];
    const float* Aq     = (const float*)d_in[8];
    const float* Bq     = (const float*)d_in[9];
    const float* Wo     = (const float*)d_in[10];
    const float* bo     = (const float*)d_in[11];
    const float* Ao     = (const float*)d_in[12];
    const float* Bo     = (const float*)d_in[13];
    const float* W1     = (const float*)d_in[14];
    const float* b1     = (const float*)d_in[15];
    const float* W2     = (const float*)d_in[16];
    const float* b2     = (const float*)d_in[17];
    const float* ln1s   = (const float*)d_in[18];
    const float* ln1b   = (const float*)d_in[19];
    const float* ln2s   = (const float*)d_in[20];
    const float* ln2b   = (const float*)d_in[21];
    const float* lnfs   = (const float*)d_in[22];
    const float* lnfb   = (const float*)d_in[23];
    const float* latw   = (const float*)d_in[24];

    float *pWqkvE, *pWoE, *pA, *pX, *pQKV, *pCTX, *pG, *pHID;
    cudaGetSymbolAddress((void**)&pWqkvE, g_Wqkv_eff);
    cudaGetSymbolAddress((void**)&pWoE,   g_Wo_eff);
    cudaGetSymbolAddress((void**)&pA,     g_A);
    cudaGetSymbolAddress((void**)&pX,     g_X);
    cudaGetSymbolAddress((void**)&pQKV,   g_QKV);
    cudaGetSymbolAddress((void**)&pCTX,   g_CTX);
    cudaGetSymbolAddress((void**)&pG,     g_G);
    cudaGetSymbolAddress((void**)&pHID,   g_HID);

    k_effqkv<<<(Dc * 3 * Dc + 255) / 256, 256>>>(Wqkv, Aq, Bq);
    k_effo  <<<(Dc * Dc + 255) / 256, 256>>>(Wo, Ao, Bo);
    k_embed <<<(NR * Dc + 255) / 256, 256>>>(ids, emb);

    auto process = [&](int t0, int len) {
        int M = 2 * len;
        int gy = (M + 127) / 128;
        k_ln1<<<M, 256>>>(Wpos, ln1s, ln1b, t0, len);
        k_gemm<<<dim3(3 * Dc / 128, gy), 256>>>(pA, pWqkvE, bqkv, pQKV, t0, len, Dc, 3 * Dc, 0);
        k_attn<<<dim3((len + 3) / 4, Hc, Bc), 128>>>(t0, len);
        k_gemm<<<dim3(Dc / 128, gy), 256>>>(pCTX, pWoE, bo, pX, t0, len, Dc, Dc, GF_ADD);
        k_lng<<<M, 256>>>(pX, ln2s, ln2b, pA, t0, len);
        k_gemm<<<dim3(DFFc / 128, gy), 256>>>(pA, W1, b1, pG, t0, len, Dc, DFFc, GF_GELU);
        k_gemm<<<dim3(Dc / 128, gy), 256>>>(pG, W2, b2, pX, t0, len, DFFc, Dc, GF_ADD);
        k_lng<<<M, 256>>>(pX, lnfs, lnfb, pHID, t0, len);
    };

    // pass 0: bulk prefix [0, 512)
    process(0, 512);
    // latent slot 512 uses hid[509:512] with softmax(latent_w)
    k_latent<<<dim3(4, Bc), 256>>>(latw, 512, 3);
    process(512, 1);
    // passes 1-3: n = min(WIN, 1) = 1 -> vec = hid[tok-1]
    k_latent<<<dim3(4, Bc), 256>>>(latw, 513, 1);
    process(513, 1);
    k_latent<<<dim3(4, Bc), 256>>>(latw, 514, 1);
    process(514, 1);
    k_latent<<<dim3(4, Bc), 256>>>(latw, 515, 1);
    process(515, 1);
    // final bulk [516, 1024)
    process(516, 508);

    // fused lm_head + log-softmax partials over all 2048 rows
    k_lmh<<<dim3(VTc, NR / 128), 256>>>(emb, labels);
    k_lse<<<NR, 128>>>();
    k_final<<<1, 256>>>((float*)d_out);
}

// round 3
// speedup vs baseline: 5.0845x; 5.0845x over previous
#include <cuda_runtime.h>
#include <cuda_bf16.h>
#include <math.h>

#define Bc   2
#define Tc   1024
#define Dc   1024
#define Hc   16
#define DHc  64
#define DFFc 4096
#define Vc   32000
#define WINc 3
#define Rc   8
#define VTc  250
#define NR   2048

#define GF_ADD     1
#define GF_GELU    2
#define GF_STOREBF 4

typedef __nv_bfloat16 bf16;

// ---------------- device scratch ----------------
__device__ bf16  g_Wqkv_h[Dc * 3 * Dc];
__device__ bf16  g_Wo_h[Dc * Dc];
__device__ bf16  g_W1h[Dc * DFFc];
__device__ bf16  g_W2h[DFFc * Dc];
__device__ bf16  g_embh[Vc * Dc];
__device__ float g_E[NR * Dc];
__device__ float g_X[NR * Dc];
__device__ bf16  g_Ah[NR * Dc];
__device__ float g_QKV[NR * 3 * Dc];
__device__ bf16  g_CTXh[NR * Dc];
__device__ bf16  g_Gh[NR * DFFc];
__device__ float g_HID[NR * Dc];
__device__ bf16  g_HIDh[NR * Dc];
__device__ float g_partM[NR * VTc];
__device__ float g_partS[NR * VTc];
__device__ float g_labelLogit[NR];
__device__ float g_nll[NR];

// ---------------- helpers ----------------
__device__ __forceinline__ float blockReduceSum(float v, float* sh) {
    int tid = threadIdx.x;
    for (int o = 16; o > 0; o >>= 1) {
        v += __shfl_xor_sync(0xffffffffu, v, o);
    }
    if ((tid & 31) == 0) {
        sh[tid >> 5] = v;
    }
    __syncthreads();
    if (tid < 32) {
        float x = (tid < (int)(blockDim.x >> 5)) ? sh[tid] : 0.f;
        for (int o = 16; o > 0; o >>= 1) {
            x += __shfl_xor_sync(0xffffffffu, x, o);
        }
        if (tid == 0) {
            sh[0] = x;
        }
    }
    __syncthreads();
    float r = sh[0];
    __syncthreads();
    return r;
}

__device__ __forceinline__ float gelu_tanh(float x) {
    float x3 = x * x * x;
    return 0.5f * x * (1.f + tanhf(0.7978845608028654f * (x + 0.044715f * x3)));
}

__device__ __forceinline__ unsigned smemu32(const void* p) {
    return (unsigned)__cvta_generic_to_shared(p);
}

__device__ __forceinline__ void ldsm_x4(unsigned& r0, unsigned& r1, unsigned& r2, unsigned& r3, unsigned addr) {
    asm volatile("ldmatrix.sync.aligned.m8n8.x4.shared.b16 {%0,%1,%2,%3}, [%4];\n"
                 : "=r"(r0), "=r"(r1), "=r"(r2), "=r"(r3) : "r"(addr));
}

__device__ __forceinline__ void ldsm_x2(unsigned& r0, unsigned& r1, unsigned addr) {
    asm volatile("ldmatrix.sync.aligned.m8n8.x2.shared.b16 {%0,%1}, [%2];\n"
                 : "=r"(r0), "=r"(r1) : "r"(addr));
}

__device__ __forceinline__ void ldsm_x2t(unsigned& r0, unsigned& r1, unsigned addr) {
    asm volatile("ldmatrix.sync.aligned.m8n8.x2.trans.shared.b16 {%0,%1}, [%2];\n"
                 : "=r"(r0), "=r"(r1) : "r"(addr));
}

__device__ __forceinline__ void mma_bf16(float* c, const unsigned* a, const unsigned* b) {
    asm volatile(
        "mma.sync.aligned.m16n8k16.row.col.f32.bf16.bf16.f32 "
        "{%0,%1,%2,%3}, {%4,%5,%6,%7}, {%8,%9}, {%0,%1,%2,%3};\n"
        : "+f"(c[0]), "+f"(c[1]), "+f"(c[2]), "+f"(c[3])
        : "r"(a[0]), "r"(a[1]), "r"(a[2]), "r"(a[3]), "r"(b[0]), "r"(b[1]));
}

// ---------------- weight merge + convert ----------------
__global__ void k_effqkv(const float* __restrict__ W, const float* __restrict__ Aq,
                         const float* __restrict__ Bq) {
    int i = blockIdx.x * 256 + threadIdx.x;
    if (i >= Dc * 3 * Dc) {
        return;
    }
    int d = i / (3 * Dc);
    int j = i - d * (3 * Dc);
    float acc = 0.f;
    for (int r = 0; r < Rc; r++) {
        acc += Aq[d * Rc + r] * Bq[r * 3 * Dc + j];
    }
    g_Wqkv_h[i] = __float2bfloat16(W[i] + 2.0f * acc);
}

__global__ void k_effo(const float* __restrict__ W, const float* __restrict__ Ao,
                       const float* __restrict__ Bo) {
    int i = blockIdx.x * 256 + threadIdx.x;
    if (i >= Dc * Dc) {
        return;
    }
    int d = i / Dc;
    int j = i - d * Dc;
    float acc = 0.f;
    for (int r = 0; r < Rc; r++) {
        acc += Ao[d * Rc + r] * Bo[r * Dc + j];
    }
    g_Wo_h[i] = __float2bfloat16(W[i] + 2.0f * acc);
}

__global__ void k_cvt(const float* __restrict__ src, bf16* __restrict__ dst, int n) {
    int i = (blockIdx.x * 256 + threadIdx.x) * 4;
    if (i >= n) {
        return;
    }
    float4 v = *(const float4*)(src + i);
    dst[i + 0] = __float2bfloat16(v.x);
    dst[i + 1] = __float2bfloat16(v.y);
    dst[i + 2] = __float2bfloat16(v.z);
    dst[i + 3] = __float2bfloat16(v.w);
}

__global__ void k_embed(const int* __restrict__ ids, const float* __restrict__ emb) {
    int i = blockIdx.x * 256 + threadIdx.x;
    if (i >= NR * Dc) {
        return;
    }
    int rid = i >> 10;
    int d = i & 1023;
    g_E[i] = emb[(size_t)ids[rid] * Dc + d];
}

// ---------------- LN kernels ----------------
__global__ void k_ln1(const float* __restrict__ Wpos, const float* __restrict__ s,
                      const float* __restrict__ bb, int t0, int len) {
    __shared__ float sh[32];
    int r = blockIdx.x;
    int b = r / len;
    int t = t0 + (r - b * len);
    size_t rid = (size_t)b * Tc + t;
    int tid = threadIdx.x;
    float v[4];
    float sum = 0.f;
    for (int i = 0; i < 4; i++) {
        int d = tid + i * 256;
        float x = g_E[rid * Dc + d] + Wpos[(size_t)t * Dc + d];
        v[i] = x;
        sum += x;
    }
    sum = blockReduceSum(sum, sh);
    float mean = sum * (1.f / Dc);
    float sq = 0.f;
    for (int i = 0; i < 4; i++) {
        float dd = v[i] - mean;
        sq += dd * dd;
    }
    sq = blockReduceSum(sq, sh);
    float inv = rsqrtf(sq * (1.f / Dc) + 1e-5f);
    for (int i = 0; i < 4; i++) {
        int d = tid + i * 256;
        g_X[rid * Dc + d] = v[i];
        g_Ah[rid * Dc + d] = __float2bfloat16((v[i] - mean) * inv * s[d] + bb[d]);
    }
}

__global__ void k_lng(const float* __restrict__ in, const float* __restrict__ s,
                      const float* __restrict__ bb, bf16* __restrict__ outh,
                      float* __restrict__ outf, int t0, int len) {
    __shared__ float sh[32];
    int r = blockIdx.x;
    int b = r / len;
    int t = t0 + (r - b * len);
    size_t rid = (size_t)b * Tc + t;
    int tid = threadIdx.x;
    float v[4];
    float sum = 0.f;
    for (int i = 0; i < 4; i++) {
        float x = in[rid * Dc + tid + i * 256];
        v[i] = x;
        sum += x;
    }
    sum = blockReduceSum(sum, sh);
    float mean = sum * (1.f / Dc);
    float sq = 0.f;
    for (int i = 0; i < 4; i++) {
        float dd = v[i] - mean;
        sq += dd * dd;
    }
    sq = blockReduceSum(sq, sh);
    float inv = rsqrtf(sq * (1.f / Dc) + 1e-5f);
    for (int i = 0; i < 4; i++) {
        int d = tid + i * 256;
        float o = (v[i] - mean) * inv * s[d] + bb[d];
        outh[rid * Dc + d] = __float2bfloat16(o);
        if (outf != nullptr) {
            outf[rid * Dc + d] = o;
        }
    }
}

// ---------------- bf16 tensor-core GEMM ----------------
__global__ __launch_bounds__(256, 2) void k_gemm(
    const bf16* __restrict__ A, const bf16* __restrict__ Bw,
    const float* __restrict__ bias, float* __restrict__ Cf, bf16* __restrict__ Cb,
    int t0, int len, int K, int N, int flags)
{
    __shared__ bf16 As[128][40];
    __shared__ bf16 Bs[32][136];
    int tid = threadIdx.x;
    int lane = tid & 31;
    int warp = tid >> 5;
    int wy = warp >> 2;
    int wx = warp & 3;
    int brow = blockIdx.y * 128;
    int bcol = blockIdx.x * 128;
    int M = 2 * len;

    int lrow = tid >> 1;
    int lcol = (tid & 1) * 16;
    const bf16* Aptr = nullptr;
    int r0 = brow + lrow;
    if (r0 < M) {
        int b = r0 / len;
        size_t rid = (size_t)b * Tc + t0 + (r0 - b * len);
        Aptr = A + rid * (size_t)K + lcol;
    }
    int bwr = tid >> 3;
    int bwc = (tid & 7) * 16;
    const bf16* Bptr = Bw + (size_t)bwr * N + bcol + bwc;

    float acc[4][4][4];
    for (int i = 0; i < 4; i++) {
        for (int j = 0; j < 4; j++) {
            for (int r = 0; r < 4; r++) {
                acc[i][j][r] = 0.f;
            }
        }
    }

    uint4 z4;
    z4.x = 0; z4.y = 0; z4.z = 0; z4.w = 0;
    uint4 av0 = Aptr ? *(const uint4*)(Aptr) : z4;
    uint4 av1 = Aptr ? *(const uint4*)(Aptr + 8) : z4;
    uint4 bv0 = *(const uint4*)(Bptr);
    uint4 bv1 = *(const uint4*)(Bptr + 8);

    for (int k0 = 0; k0 < K; k0 += 32) {
        *(uint4*)&As[lrow][lcol] = av0;
        *(uint4*)&As[lrow][lcol + 8] = av1;
        *(uint4*)&Bs[bwr][bwc] = bv0;
        *(uint4*)&Bs[bwr][bwc + 8] = bv1;
        __syncthreads();
        int kn = k0 + 32;
        if (kn < K) {
            av0 = Aptr ? *(const uint4*)(Aptr + kn) : z4;
            av1 = Aptr ? *(const uint4*)(Aptr + kn + 8) : z4;
            bv0 = *(const uint4*)(Bptr + (size_t)kn * N);
            bv1 = *(const uint4*)(Bptr + (size_t)kn * N + 8);
        }
        for (int kc = 0; kc < 32; kc += 16) {
            unsigned af[4][4];
            unsigned bfr[4][2];
            for (int i = 0; i < 4; i++) {
                unsigned a = smemu32(&As[wy * 64 + i * 16 + (lane & 15)][kc + 8 * (lane >> 4)]);
                ldsm_x4(af[i][0], af[i][1], af[i][2], af[i][3], a);
            }
            for (int j = 0; j < 4; j++) {
                unsigned a = smemu32(&Bs[kc + (lane & 15)][wx * 32 + j * 8]);
                ldsm_x2t(bfr[j][0], bfr[j][1], a);
            }
            for (int i = 0; i < 4; i++) {
                for (int j = 0; j < 4; j++) {
                    mma_bf16(acc[i][j], af[i], bfr[j]);
                }
            }
        }
        __syncthreads();
    }

    for (int i = 0; i < 4; i++) {
        for (int r2 = 0; r2 < 2; r2++) {
            int row = brow + wy * 64 + i * 16 + (lane >> 2) + r2 * 8;
            if (row < M) {
                int b = row / len;
                size_t rid = (size_t)b * Tc + t0 + (row - b * len);
                for (int j = 0; j < 4; j++) {
                    for (int c2 = 0; c2 < 2; c2++) {
                        int col = bcol + wx * 32 + j * 8 + (lane & 3) * 2 + c2;
                        float v = acc[i][j][r2 * 2 + c2] + bias[col];
                        if (flags & GF_GELU) {
                            v = gelu_tanh(v);
                        }
                        if (flags & GF_STOREBF) {
                            Cb[rid * (size_t)N + col] = __float2bfloat16(v);
                        } else if (flags & GF_ADD) {
                            Cf[rid * (size_t)N + col] += v;
                        } else {
                            Cf[rid * (size_t)N + col] = v;
                        }
                    }
                }
            }
        }
    }
}

// ---------------- attention ----------------
__global__ void k_attn(int t0, int len) {
    __shared__ float Ks[64][64];
    __shared__ float Vs[64][64];
    int tid = threadIdx.x;
    int warp = tid >> 5;
    int lane = tid & 31;
    int tq = t0 + blockIdx.x * 8 + warp;
    int h = blockIdx.y;
    int b = blockIdx.z;
    bool valid = (tq < t0 + len);
    float qx = 0.f;
    float qy = 0.f;
    if (valid) {
        const float* qp = g_QKV + ((size_t)(b * Tc + tq) * 3 * Dc) + h * DHc;
        float2 q2 = ((const float2*)qp)[lane];
        qx = q2.x;
        qy = q2.y;
    }
    float l = 0.f;
    float a0 = 0.f;
    float a1 = 0.f;
    int tmaxb = t0 + (int)blockIdx.x * 8 + 7;
    if (tmaxb > t0 + len - 1) {
        tmaxb = t0 + len - 1;
    }
    for (int s0 = 0; s0 <= tmaxb; s0 += 64) {
        int rows = tmaxb + 1 - s0;
        if (rows > 64) {
            rows = 64;
        }
        for (int i = tid; i < rows * 16; i += 256) {
            int rr = i >> 4;
            int seg = i & 15;
            const float* base = g_QKV + ((size_t)(b * Tc + s0 + rr) * 3 * Dc) + Dc + h * DHc;
            ((float4*)&Ks[rr][0])[seg] = ((const float4*)base)[seg];
            ((float4*)&Vs[rr][0])[seg] = ((const float4*)(base + Dc))[seg];
        }
        __syncthreads();
        int send = 0;
        if (valid) {
            send = tq + 1 - s0;
            if (send > rows) {
                send = rows;
            }
        }
        for (int s = 0; s < send; s++) {
            float2 kv = ((const float2*)&Ks[s][0])[lane];
            float p = qx * kv.x + qy * kv.y;
            for (int o = 16; o > 0; o >>= 1) {
                p += __shfl_xor_sync(0xffffffffu, p, o);
            }
            float w = __expf(p * 0.125f);
            float2 vv = ((const float2*)&Vs[s][0])[lane];
            l += w;
            a0 += w * vv.x;
            a1 += w * vv.y;
        }
        __syncthreads();
    }
    if (valid) {
        float inv = 1.f / l;
        bf16* cp = g_CTXh + ((size_t)(b * Tc + tq) * Dc) + h * DHc;
        cp[lane * 2] = __float2bfloat16(a0 * inv);
        cp[lane * 2 + 1] = __float2bfloat16(a1 * inv);
    }
}

// ---------------- latent scatter ----------------
__global__ void k_latent(const float* __restrict__ latw, int tok, int n) {
    int b = blockIdx.y;
    int d = blockIdx.x * 256 + threadIdx.x;
    if (d >= Dc) {
        return;
    }
    float w[WINc];
    float mx = -1e30f;
    for (int i = 0; i < n; i++) {
        w[i] = latw[WINc - n + i];
        if (w[i] > mx) {
            mx = w[i];
        }
    }
    float ssum = 0.f;
    for (int i = 0; i < n; i++) {
        w[i] = expf(w[i] - mx);
        ssum += w[i];
    }
    float acc = 0.f;
    for (int i = 0; i < n; i++) {
        acc += (w[i] / ssum) * g_HID[(size_t)(b * Tc + tok - n + i) * Dc + d];
    }
    g_E[(size_t)(b * Tc + tok) * Dc + d] = acc;
}

// ---------------- lm_head fused with log-softmax partials ----------------
__global__ __launch_bounds__(256, 2) void k_lmh(const int* __restrict__ labels) {
    __shared__ bf16 As[128][40];
    __shared__ bf16 Es[128][40];
    __shared__ float redM[128][4];
    __shared__ float redS[128][4];
    int tid = threadIdx.x;
    int lane = tid & 31;
    int warp = tid >> 5;
    int wy = warp >> 2;
    int wx = warp & 3;
    int vb = blockIdx.x * 128;
    int rb = blockIdx.y * 128;

    int lrow = tid >> 1;
    int lcol = (tid & 1) * 16;
    const bf16* Aptr = g_HIDh + (size_t)(rb + lrow) * Dc + lcol;
    const bf16* Eptr = g_embh + (size_t)(vb + lrow) * Dc + lcol;

    float acc[4][4][4];
    for (int i = 0; i < 4; i++) {
        for (int j = 0; j < 4; j++) {
            for (int r = 0; r < 4; r++) {
                acc[i][j][r] = 0.f;
            }
        }
    }

    uint4 av0 = *(const uint4*)(Aptr);
    uint4 av1 = *(const uint4*)(Aptr + 8);
    uint4 ev0 = *(const uint4*)(Eptr);
    uint4 ev1 = *(const uint4*)(Eptr + 8);

    for (int k0 = 0; k0 < Dc; k0 += 32) {
        *(uint4*)&As[lrow][lcol] = av0;
        *(uint4*)&As[lrow][lcol + 8] = av1;
        *(uint4*)&Es[lrow][lcol] = ev0;
        *(uint4*)&Es[lrow][lcol + 8] = ev1;
        __syncthreads();
        int kn = k0 + 32;
        if (kn < Dc) {
            av0 = *(const uint4*)(Aptr + kn);
            av1 = *(const uint4*)(Aptr + kn + 8);
            ev0 = *(const uint4*)(Eptr + kn);
            ev1 = *(const uint4*)(Eptr + kn + 8);
        }
        for (int kc = 0; kc < 32; kc += 16) {
            unsigned af[4][4];
            unsigned bfr[4][2];
            for (int i = 0; i < 4; i++) {
                unsigned a = smemu32(&As[wy * 64 + i * 16 + (lane & 15)][kc + 8 * (lane >> 4)]);
                ldsm_x4(af[i][0], af[i][1], af[i][2], af[i][3], a);
            }
            for (int j = 0; j < 4; j++) {
                unsigned a = smemu32(&Es[wx * 32 + j * 8 + (lane & 7)][kc + ((lane >> 3) & 1) * 8]);
                ldsm_x2(bfr[j][0], bfr[j][1], a);
            }
            for (int i = 0; i < 4; i++) {
                for (int j = 0; j < 4; j++) {
                    mma_bf16(acc[i][j], af[i], bfr[j]);
                }
            }
        }
        __syncthreads();
    }

    for (int i = 0; i < 4; i++) {
        for (int r2 = 0; r2 < 2; r2++) {
            int rowl = wy * 64 + i * 16 + (lane >> 2) + r2 * 8;
            int rid = rb + rowl;
            float m = -1e30f;
            for (int j = 0; j < 4; j++) {
                for (int c2 = 0; c2 < 2; c2++) {
                    float x = acc[i][j][r2 * 2 + c2];
                    if (x > m) {
                        m = x;
                    }
                }
            }
            float s = 0.f;
            for (int j = 0; j < 4; j++) {
                for (int c2 = 0; c2 < 2; c2++) {
                    s += __expf(acc[i][j][r2 * 2 + c2] - m);
                }
            }
            for (int o = 1; o < 4; o <<= 1) {
                float om = __shfl_xor_sync(0xffffffffu, m, o);
                float os = __shfl_xor_sync(0xffffffffu, s, o);
                float nm = fmaxf(m, om);
                s = s * __expf(m - nm) + os * __expf(om - nm);
                m = nm;
            }
            if ((lane & 3) == 0) {
                redM[rowl][wx] = m;
                redS[rowl][wx] = s;
            }
            int t = rid & (Tc - 1);
            int b = rid >> 10;
            if (t < Tc - 1) {
                int lab = labels[b * Tc + t + 1];
                for (int j = 0; j < 4; j++) {
                    for (int c2 = 0; c2 < 2; c2++) {
                        int col = vb + wx * 32 + j * 8 + (lane & 3) * 2 + c2;
                        if (col == lab) {
                            g_labelLogit[rid] = acc[i][j][r2 * 2 + c2];
                        }
                    }
                }
            }
        }
    }
    __syncthreads();
    if (tid < 128) {
        float m = redM[tid][0];
        float s = redS[tid][0];
        for (int w2 = 1; w2 < 4; w2++) {
            float om = redM[tid][w2];
            float os = redS[tid][w2];
            float nm = fmaxf(m, om);
            s = s * __expf(m - nm) + os * __expf(om - nm);
            m = nm;
        }
        int rid = rb + tid;
        g_partM[(size_t)rid * VTc + blockIdx.x] = m;
        g_partS[(size_t)rid * VTc + blockIdx.x] = s;
    }
}

__global__ void k_lse(void) {
    __shared__ float sm[128];
    int row = blockIdx.x;
    int t = row & (Tc - 1);
    int tid = threadIdx.x;
    if (t == Tc - 1) {
        if (tid == 0) {
            g_nll[row] = 0.f;
        }
        return;
    }
    float M = -1e30f;
    for (int i = tid; i < VTc; i += 128) {
        float x = g_partM[(size_t)row * VTc + i];
        if (x > M) {
            M = x;
        }
    }
    sm[tid] = M;
    __syncthreads();
    for (int s = 64; s > 0; s >>= 1) {
        if (tid < s) {
            sm[tid] = fmaxf(sm[tid], sm[tid + s]);
        }
        __syncthreads();
    }
    M = sm[0];
    __syncthreads();
    float S = 0.f;
    for (int i = tid; i < VTc; i += 128) {
        S += g_partS[(size_t)row * VTc + i] * expf(g_partM[(size_t)row * VTc + i] - M);
    }
    sm[tid] = S;
    __syncthreads();
    for (int s = 64; s > 0; s >>= 1) {
        if (tid < s) {
            sm[tid] += sm[tid + s];
        }
        __syncthreads();
    }
    if (tid == 0) {
        g_nll[row] = M + logf(sm[0]) - g_labelLogit[row];
    }
}

__global__ void k_final(float* out) {
    __shared__ float sh[32];
    float s = 0.f;
    for (int i = threadIdx.x; i < NR; i += 256) {
        s += g_nll[i];
    }
    s = blockReduceSum(s, sh);
    if (threadIdx.x == 0) {
        out[0] = s / (float)(Bc * (Tc - 1));
    }
}

// ---------------- host orchestration ----------------
static void run_block(const bf16* pAh, const bf16* pWqkvH, const float* bqkv,
                      float* pQKV, const bf16* pCTXh, const bf16* pWoH,
                      const float* bo, float* pX, const float* ln2s, const float* ln2b,
                      const bf16* pW1H, const float* b1, bf16* pGh,
                      const bf16* pW2H, const float* b2,
                      const float* lnfs, const float* lnfb, bf16* pHIDh, float* pHID,
                      const float* Wpos, const float* ln1s, const float* ln1b,
                      int t0, int len)
{
    int M = 2 * len;
    int gy = (M + 127) / 128;
    k_ln1<<<M, 256>>>(Wpos, ln1s, ln1b, t0, len);
    k_gemm<<<dim3(3 * Dc / 128, gy), 256>>>(pAh, pWqkvH, bqkv, pQKV, nullptr, t0, len, Dc, 3 * Dc, 0);
    k_attn<<<dim3((len + 7) / 8, Hc, Bc), 256>>>(t0, len);
    k_gemm<<<dim3(Dc / 128, gy), 256>>>(pCTXh, pWoH, bo, pX, nullptr, t0, len, Dc, Dc, GF_ADD);
    k_lng<<<M, 256>>>(pX, ln2s, ln2b, (bf16*)pAh, nullptr, t0, len);
    k_gemm<<<dim3(DFFc / 128, gy), 256>>>(pAh, pW1H, b1, nullptr, pGh, t0, len, Dc, DFFc, GF_GELU | GF_STOREBF);
    k_gemm<<<dim3(Dc / 128, gy), 256>>>(pGh, pW2H, b2, pX, nullptr, t0, len, DFFc, Dc, GF_ADD);
    k_lng<<<M, 256>>>(pX, lnfs, lnfb, pHIDh, pHID, t0, len);
}

extern "C" void kernel_launch(void* const* d_in, const int* in_sizes, int n_in,
                              void* d_out, int out_size) {
    const int* ids = (const int*)d_in[0];
    const int* labels = (const int*)d_in[2];
    const float* emb = (const float*)d_in[4];
    const float* Wpos = (const float*)d_in[5];
    const float* Wqkv = (const float*)d_in[6];
    const float* bqkv = (const float*)d_in[7];
    const float* Aq = (const float*)d_in[8];
    const float* Bq = (const float*)d_in[9];
    const float* Wo = (const float*)d_in[10];
    const float* bo = (const float*)d_in[11];
    const float* Ao = (const float*)d_in[12];
    const float* Bo = (const float*)d_in[13];
    const float* W1 = (const float*)d_in[14];
    const float* b1 = (const float*)d_in[15];
    const float* W2 = (const float*)d_in[16];
    const float* b2 = (const float*)d_in[17];
    const float* ln1s = (const float*)d_in[18];
    const float* ln1b = (const float*)d_in[19];
    const float* ln2s = (const float*)d_in[20];
    const float* ln2b = (const float*)d_in[21];
    const float* lnfs = (const float*)d_in[22];
    const float* lnfb = (const float*)d_in[23];
    const float* latw = (const float*)d_in[24];

    void* vp = nullptr;
    cudaGetSymbolAddress(&vp, g_Wqkv_h);
    bf16* pWqkvH = (bf16*)vp;
    cudaGetSymbolAddress(&vp, g_Wo_h);
    bf16* pWoH = (bf16*)vp;
    cudaGetSymbolAddress(&vp, g_W1h);
    bf16* pW1H = (bf16*)vp;
    cudaGetSymbolAddress(&vp, g_W2h);
    bf16* pW2H = (bf16*)vp;
    cudaGetSymbolAddress(&vp, g_embh);
    bf16* pEmbH = (bf16*)vp;
    cudaGetSymbolAddress(&vp, g_Ah);
    bf16* pAh = (bf16*)vp;
    cudaGetSymbolAddress(&vp, g_CTXh);
    bf16* pCTXh = (bf16*)vp;
    cudaGetSymbolAddress(&vp, g_Gh);
    bf16* pGh = (bf16*)vp;
    cudaGetSymbolAddress(&vp, g_HIDh);
    bf16* pHIDh = (bf16*)vp;
    cudaGetSymbolAddress(&vp, g_X);
    float* pX = (float*)vp;
    cudaGetSymbolAddress(&vp, g_QKV);
    float* pQKV = (float*)vp;
    cudaGetSymbolAddress(&vp, g_HID);
    float* pHID = (float*)vp;

    k_effqkv<<<(Dc * 3 * Dc + 255) / 256, 256>>>(Wqkv, Aq, Bq);
    k_effo<<<(Dc * Dc + 255) / 256, 256>>>(Wo, Ao, Bo);
    k_cvt<<<(Dc * DFFc / 4 + 255) / 256, 256>>>(W1, pW1H, Dc * DFFc);
    k_cvt<<<(DFFc * Dc / 4 + 255) / 256, 256>>>(W2, pW2H, DFFc * Dc);
    k_cvt<<<(Vc * Dc / 4 + 255) / 256, 256>>>(emb, pEmbH, Vc * Dc);
    k_embed<<<(NR * Dc + 255) / 256, 256>>>(ids, emb);

    run_block(pAh, pWqkvH, bqkv, pQKV, pCTXh, pWoH, bo, pX, ln2s, ln2b,
              pW1H, b1, pGh, pW2H, b2, lnfs, lnfb, pHIDh, pHID,
              Wpos, ln1s, ln1b, 0, 512);
    k_latent<<<dim3(4, Bc), 256>>>(latw, 512, 3);
    run_block(pAh, pWqkvH, bqkv, pQKV, pCTXh, pWoH, bo, pX, ln2s, ln2b,
              pW1H, b1, pGh, pW2H, b2, lnfs, lnfb, pHIDh, pHID,
              Wpos, ln1s, ln1b, 512, 1);
    k_latent<<<dim3(4, Bc), 256>>>(latw, 513, 1);
    run_block(pAh, pWqkvH, bqkv, pQKV, pCTXh, pWoH, bo, pX, ln2s, ln2b,
              pW1H, b1, pGh, pW2H, b2, lnfs, lnfb, pHIDh, pHID,
              Wpos, ln1s, ln1b, 513, 1);
    k_latent<<<dim3(4, Bc), 256>>>(latw, 514, 1);
    run_block(pAh, pWqkvH, bqkv, pQKV, pCTXh, pWoH, bo, pX, ln2s, ln2b,
              pW1H, b1, pGh, pW2H, b2, lnfs, lnfb, pHIDh, pHID,
              Wpos, ln1s, ln1b, 514, 1);
    k_latent<<<dim3(4, Bc), 256>>>(latw, 515, 1);
    run_block(pAh, pWqkvH, bqkv, pQKV, pCTXh, pWoH, bo, pX, ln2s, ln2b,
              pW1H, b1, pGh, pW2H, b2, lnfs, lnfb, pHIDh, pHID,
              Wpos, ln1s, ln1b, 515, 1);
    run_block(pAh, pWqkvH, bqkv, pQKV, pCTXh, pWoH, bo, pX, ln2s, ln2b,
              pW1H, b1, pGh, pW2H, b2, lnfs, lnfb, pHIDh, pHID,
              Wpos, ln1s, ln1b, 516, 508);

    k_lmh<<<dim3(VTc, NR / 128), 256>>>(labels);
    k_lse<<<NR, 128>>>();
    k_final<<<1, 256>>>((float*)d_out);
}

// round 4
// speedup vs baseline: 6.8002x; 1.3374x over previous
#include <cuda_runtime.h>
#include <cuda_bf16.h>
#include <math.h>

#define Bc   2
#define Tc   1024
#define Dc   1024
#define Hc   16
#define DHc  64
#define DFFc 4096
#define Vc   32000
#define WINc 3
#define Rc   8
#define VTc  125
#define NR   2048

#define GF_ADD     1
#define GF_GELU    2
#define GF_STOREBF 4
#define GF_BOTH    8

typedef __nv_bfloat16 bf16;

// ---------------- device scratch ----------------
__device__ bf16  g_Wqkv_h[Dc * 3 * Dc];
__device__ bf16  g_Wo_h[Dc * Dc];
__device__ bf16  g_W1h[Dc * DFFc];
__device__ bf16  g_W2h[DFFc * Dc];
__device__ bf16  g_embh[Vc * Dc];
__device__ float g_E[NR * Dc];
__device__ float g_X[NR * Dc];
__device__ bf16  g_Ah[NR * Dc];
__device__ float g_QKV[NR * 3 * Dc];
__device__ bf16  g_QKVh[NR * 3 * Dc];
__device__ bf16  g_CTXh[NR * Dc];
__device__ bf16  g_Gh[NR * DFFc];
__device__ float g_HID[NR * Dc];
__device__ bf16  g_HIDh[NR * Dc];
__device__ float g_partM[NR * VTc];
__device__ float g_partS[NR * VTc];
__device__ float g_labelLogit[NR];
__device__ float g_nll[NR];

// ---------------- helpers ----------------
__device__ __forceinline__ float blockReduceSum(float v, float* sh) {
    int tid = threadIdx.x;
    for (int o = 16; o > 0; o >>= 1) {
        v += __shfl_xor_sync(0xffffffffu, v, o);
    }
    if ((tid & 31) == 0) {
        sh[tid >> 5] = v;
    }
    __syncthreads();
    if (tid < 32) {
        float x = (tid < (int)(blockDim.x >> 5)) ? sh[tid] : 0.f;
        for (int o = 16; o > 0; o >>= 1) {
            x += __shfl_xor_sync(0xffffffffu, x, o);
        }
        if (tid == 0) {
            sh[0] = x;
        }
    }
    __syncthreads();
    float r = sh[0];
    __syncthreads();
    return r;
}

__device__ __forceinline__ float gelu_tanh(float x) {
    float x3 = x * x * x;
    return 0.5f * x * (1.f + tanhf(0.7978845608028654f * (x + 0.044715f * x3)));
}

__device__ __forceinline__ unsigned smemu32(const void* p) {
    return (unsigned)__cvta_generic_to_shared(p);
}

__device__ __forceinline__ void ldsm_x4(unsigned& r0, unsigned& r1, unsigned& r2, unsigned& r3, unsigned addr) {
    asm volatile("ldmatrix.sync.aligned.m8n8.x4.shared.b16 {%0,%1,%2,%3}, [%4];\n"
                 : "=r"(r0), "=r"(r1), "=r"(r2), "=r"(r3) : "r"(addr));
}

__device__ __forceinline__ void ldsm_x2(unsigned& r0, unsigned& r1, unsigned addr) {
    asm volatile("ldmatrix.sync.aligned.m8n8.x2.shared.b16 {%0,%1}, [%2];\n"
                 : "=r"(r0), "=r"(r1) : "r"(addr));
}

__device__ __forceinline__ void ldsm_x2t(unsigned& r0, unsigned& r1, unsigned addr) {
    asm volatile("ldmatrix.sync.aligned.m8n8.x2.trans.shared.b16 {%0,%1}, [%2];\n"
                 : "=r"(r0), "=r"(r1) : "r"(addr));
}

__device__ __forceinline__ void mma_bf16(float* c, const unsigned* a, const unsigned* b) {
    asm volatile(
        "mma.sync.aligned.m16n8k16.row.col.f32.bf16.bf16.f32 "
        "{%0,%1,%2,%3}, {%4,%5,%6,%7}, {%8,%9}, {%0,%1,%2,%3};\n"
        : "+f"(c[0]), "+f"(c[1]), "+f"(c[2]), "+f"(c[3])
        : "r"(a[0]), "r"(a[1]), "r"(a[2]), "r"(a[3]), "r"(b[0]), "r"(b[1]));
}

__device__ __forceinline__ unsigned packbf2(float lo, float hi) {
    __nv_bfloat162 p = __floats2bfloat162_rn(lo, hi);
    return *(unsigned*)&p;
}

// ---------------- weight merge + convert ----------------
__global__ void k_effqkv(const float* __restrict__ W, const float* __restrict__ Aq,
                         const float* __restrict__ Bq) {
    int i = blockIdx.x * 256 + threadIdx.x;
    if (i >= Dc * 3 * Dc) {
        return;
    }
    int d = i / (3 * Dc);
    int j = i - d * (3 * Dc);
    float acc = 0.f;
    for (int r = 0; r < Rc; r++) {
        acc += Aq[d * Rc + r] * Bq[r * 3 * Dc + j];
    }
    g_Wqkv_h[i] = __float2bfloat16(W[i] + 2.0f * acc);
}

__global__ void k_effo(const float* __restrict__ W, const float* __restrict__ Ao,
                       const float* __restrict__ Bo) {
    int i = blockIdx.x * 256 + threadIdx.x;
    if (i >= Dc * Dc) {
        return;
    }
    int d = i / Dc;
    int j = i - d * Dc;
    float acc = 0.f;
    for (int r = 0; r < Rc; r++) {
        acc += Ao[d * Rc + r] * Bo[r * Dc + j];
    }
    g_Wo_h[i] = __float2bfloat16(W[i] + 2.0f * acc);
}

__global__ void k_cvt(const float* __restrict__ src, bf16* __restrict__ dst, int n) {
    int i = (blockIdx.x * 256 + threadIdx.x) * 4;
    if (i >= n) {
        return;
    }
    float4 v = *(const float4*)(src + i);
    dst[i + 0] = __float2bfloat16(v.x);
    dst[i + 1] = __float2bfloat16(v.y);
    dst[i + 2] = __float2bfloat16(v.z);
    dst[i + 3] = __float2bfloat16(v.w);
}

__global__ void k_embed(const int* __restrict__ ids, const float* __restrict__ emb) {
    int i = blockIdx.x * 256 + threadIdx.x;
    if (i >= NR * Dc) {
        return;
    }
    int rid = i >> 10;
    int d = i & 1023;
    g_E[i] = emb[(size_t)ids[rid] * Dc + d];
}

// ---------------- LN kernels ----------------
__global__ void k_ln1(const float* __restrict__ Wpos, const float* __restrict__ s,
                      const float* __restrict__ bb, int t0, int len) {
    __shared__ float sh[32];
    int r = blockIdx.x;
    int b = r / len;
    int t = t0 + (r - b * len);
    size_t rid = (size_t)b * Tc + t;
    int tid = threadIdx.x;
    float v[4];
    float sum = 0.f;
    for (int i = 0; i < 4; i++) {
        int d = tid + i * 256;
        float x = g_E[rid * Dc + d] + Wpos[(size_t)t * Dc + d];
        v[i] = x;
        sum += x;
    }
    sum = blockReduceSum(sum, sh);
    float mean = sum * (1.f / Dc);
    float sq = 0.f;
    for (int i = 0; i < 4; i++) {
        float dd = v[i] - mean;
        sq += dd * dd;
    }
    sq = blockReduceSum(sq, sh);
    float inv = rsqrtf(sq * (1.f / Dc) + 1e-5f);
    for (int i = 0; i < 4; i++) {
        int d = tid + i * 256;
        g_X[rid * Dc + d] = v[i];
        g_Ah[rid * Dc + d] = __float2bfloat16((v[i] - mean) * inv * s[d] + bb[d]);
    }
}

__global__ void k_lng(const float* __restrict__ in, const float* __restrict__ s,
                      const float* __restrict__ bb, bf16* __restrict__ outh,
                      float* __restrict__ outf, int t0, int len) {
    __shared__ float sh[32];
    int r = blockIdx.x;
    int b = r / len;
    int t = t0 + (r - b * len);
    size_t rid = (size_t)b * Tc + t;
    int tid = threadIdx.x;
    float v[4];
    float sum = 0.f;
    for (int i = 0; i < 4; i++) {
        float x = in[rid * Dc + tid + i * 256];
        v[i] = x;
        sum += x;
    }
    sum = blockReduceSum(sum, sh);
    float mean = sum * (1.f / Dc);
    float sq = 0.f;
    for (int i = 0; i < 4; i++) {
        float dd = v[i] - mean;
        sq += dd * dd;
    }
    sq = blockReduceSum(sq, sh);
    float inv = rsqrtf(sq * (1.f / Dc) + 1e-5f);
    for (int i = 0; i < 4; i++) {
        int d = tid + i * 256;
        float o = (v[i] - mean) * inv * s[d] + bb[d];
        outh[rid * Dc + d] = __float2bfloat16(o);
        if (outf != nullptr) {
            outf[rid * Dc + d] = o;
        }
    }
}

// ---------------- bf16 tensor-core GEMM ----------------
__global__ __launch_bounds__(256, 2) void k_gemm(
    const bf16* __restrict__ A, const bf16* __restrict__ Bw,
    const float* __restrict__ bias, float* __restrict__ Cf, bf16* __restrict__ Cb,
    int t0, int len, int K, int N, int flags)
{
    __shared__ bf16 As[128][40];
    __shared__ bf16 Bs[32][136];
    int tid = threadIdx.x;
    int lane = tid & 31;
    int warp = tid >> 5;
    int wy = warp >> 2;
    int wx = warp & 3;
    int brow = blockIdx.y * 128;
    int bcol = blockIdx.x * 128;
    int M = 2 * len;

    int lrow = tid >> 1;
    int lcol = (tid & 1) * 16;
    const bf16* Aptr = nullptr;
    int r0 = brow + lrow;
    if (r0 < M) {
        int b = r0 / len;
        size_t rid = (size_t)b * Tc + t0 + (r0 - b * len);
        Aptr = A + rid * (size_t)K + lcol;
    }
    int bwr = tid >> 3;
    int bwc = (tid & 7) * 16;
    const bf16* Bptr = Bw + (size_t)bwr * N + bcol + bwc;

    float acc[4][4][4];
    for (int i = 0; i < 4; i++) {
        for (int j = 0; j < 4; j++) {
            for (int r = 0; r < 4; r++) {
                acc[i][j][r] = 0.f;
            }
        }
    }

    uint4 z4;
    z4.x = 0; z4.y = 0; z4.z = 0; z4.w = 0;
    uint4 av0 = Aptr ? *(const uint4*)(Aptr) : z4;
    uint4 av1 = Aptr ? *(const uint4*)(Aptr + 8) : z4;
    uint4 bv0 = *(const uint4*)(Bptr);
    uint4 bv1 = *(const uint4*)(Bptr + 8);

    for (int k0 = 0; k0 < K; k0 += 32) {
        *(uint4*)&As[lrow][lcol] = av0;
        *(uint4*)&As[lrow][lcol + 8] = av1;
        *(uint4*)&Bs[bwr][bwc] = bv0;
        *(uint4*)&Bs[bwr][bwc + 8] = bv1;
        __syncthreads();
        int kn = k0 + 32;
        if (kn < K) {
            av0 = Aptr ? *(const uint4*)(Aptr + kn) : z4;
            av1 = Aptr ? *(const uint4*)(Aptr + kn + 8) : z4;
            bv0 = *(const uint4*)(Bptr + (size_t)kn * N);
            bv1 = *(const uint4*)(Bptr + (size_t)kn * N + 8);
        }
        for (int kc = 0; kc < 32; kc += 16) {
            unsigned af[4][4];
            unsigned bfr[4][2];
            for (int i = 0; i < 4; i++) {
                unsigned a = smemu32(&As[wy * 64 + i * 16 + (lane & 15)][kc + 8 * (lane >> 4)]);
                ldsm_x4(af[i][0], af[i][1], af[i][2], af[i][3], a);
            }
            for (int j = 0; j < 4; j++) {
                unsigned a = smemu32(&Bs[kc + (lane & 15)][wx * 32 + j * 8]);
                ldsm_x2t(bfr[j][0], bfr[j][1], a);
            }
            for (int i = 0; i < 4; i++) {
                for (int j = 0; j < 4; j++) {
                    mma_bf16(acc[i][j], af[i], bfr[j]);
                }
            }
        }
        __syncthreads();
    }

    for (int i = 0; i < 4; i++) {
        for (int r2 = 0; r2 < 2; r2++) {
            int row = brow + wy * 64 + i * 16 + (lane >> 2) + r2 * 8;
            if (row < M) {
                int b = row / len;
                size_t rid = (size_t)b * Tc + t0 + (row - b * len);
                for (int j = 0; j < 4; j++) {
                    for (int c2 = 0; c2 < 2; c2++) {
                        int col = bcol + wx * 32 + j * 8 + (lane & 3) * 2 + c2;
                        float v = acc[i][j][r2 * 2 + c2] + bias[col];
                        if (flags & GF_GELU) {
                            v = gelu_tanh(v);
                        }
                        if (flags & GF_STOREBF) {
                            Cb[rid * (size_t)N + col] = __float2bfloat16(v);
                        } else if (flags & GF_BOTH) {
                            Cf[rid * (size_t)N + col] = v;
                            Cb[rid * (size_t)N + col] = __float2bfloat16(v);
                        } else if (flags & GF_ADD) {
                            Cf[rid * (size_t)N + col] += v;
                        } else {
                            Cf[rid * (size_t)N + col] = v;
                        }
                    }
                }
            }
        }
    }
}

// ---------------- flash attention (bulk passes): 64q x 64k tiles, bf16 mma ----------------
__global__ __launch_bounds__(128, 2) void k_flash(int t0, int len) {
    __shared__ bf16 Qs[64][72];
    __shared__ bf16 Ks[64][72];
    __shared__ bf16 Vs[64][72];
    int tid = threadIdx.x;
    int lane = tid & 31;
    int warp = tid >> 5;
    int q0 = t0 + blockIdx.x * 64;
    int h = blockIdx.y;
    int b = blockIdx.z;
    int qend = t0 + len;

    // load Q tile (zero-pad rows beyond qend)
    {
        int r = tid >> 1;
        int seg = (tid & 1) * 32;
        int q = q0 + r;
        if (q < qend) {
            const bf16* src = g_QKVh + ((size_t)(b * Tc + q) * 3 * Dc) + h * DHc + seg;
            for (int k = 0; k < 4; k++) {
                *(uint4*)&Qs[r][seg + k * 8] = *(const uint4*)(src + k * 8);
            }
        } else {
            uint4 z;
            z.x = 0; z.y = 0; z.z = 0; z.w = 0;
            for (int k = 0; k < 4; k++) {
                *(uint4*)&Qs[r][seg + k * 8] = z;
            }
        }
    }
    __syncthreads();

    int wq = warp * 16;
    unsigned aq[4][4];
    for (int kc = 0; kc < 4; kc++) {
        unsigned a = smemu32(&Qs[wq + (lane & 15)][kc * 16 + 8 * (lane >> 4)]);
        ldsm_x4(aq[kc][0], aq[kc][1], aq[kc][2], aq[kc][3], a);
    }

    float ctx[8][4];
    for (int j = 0; j < 8; j++) {
        for (int r = 0; r < 4; r++) {
            ctx[j][r] = 0.f;
        }
    }
    float lsum0 = 0.f;
    float lsum1 = 0.f;
    int qmax = q0 + 63;
    if (qmax > qend - 1) {
        qmax = qend - 1;
    }
    int row0 = q0 + wq + (lane >> 2);
    int row1 = row0 + 8;

    for (int kt0 = 0; kt0 <= qmax; kt0 += 64) {
        __syncthreads();
        {
            int r = tid >> 1;
            int seg = (tid & 1) * 32;
            const bf16* ksrc = g_QKVh + ((size_t)(b * Tc + kt0 + r) * 3 * Dc) + Dc + h * DHc + seg;
            const bf16* vsrc = ksrc + Dc;
            for (int k = 0; k < 4; k++) {
                *(uint4*)&Ks[r][seg + k * 8] = *(const uint4*)(ksrc + k * 8);
                *(uint4*)&Vs[r][seg + k * 8] = *(const uint4*)(vsrc + k * 8);
            }
        }
        __syncthreads();

        float sacc[8][4];
        for (int j = 0; j < 8; j++) {
            for (int r = 0; r < 4; r++) {
                sacc[j][r] = 0.f;
            }
        }
        for (int kc = 0; kc < 4; kc++) {
            for (int j = 0; j < 8; j++) {
                unsigned bb[2];
                unsigned a = smemu32(&Ks[j * 8 + (lane & 7)][kc * 16 + ((lane >> 3) & 1) * 8]);
                ldsm_x2(bb[0], bb[1], a);
                mma_bf16(sacc[j], aq[kc], bb);
            }
        }

        unsigned pfrag[4][4];
        int colb = kt0 + (lane & 3) * 2;
        for (int kk = 0; kk < 4; kk++) {
            int j0 = kk * 2;
            int j1 = j0 + 1;
            int c0 = colb + kk * 16;
            int c1 = c0 + 8;
            float w00 = (c0 <= row0) ? __expf(sacc[j0][0] * 0.125f) : 0.f;
            float w01 = (c0 + 1 <= row0) ? __expf(sacc[j0][1] * 0.125f) : 0.f;
            float w02 = (c0 <= row1) ? __expf(sacc[j0][2] * 0.125f) : 0.f;
            float w03 = (c0 + 1 <= row1) ? __expf(sacc[j0][3] * 0.125f) : 0.f;
            float w10 = (c1 <= row0) ? __expf(sacc[j1][0] * 0.125f) : 0.f;
            float w11 = (c1 + 1 <= row0) ? __expf(sacc[j1][1] * 0.125f) : 0.f;
            float w12 = (c1 <= row1) ? __expf(sacc[j1][2] * 0.125f) : 0.f;
            float w13 = (c1 + 1 <= row1) ? __expf(sacc[j1][3] * 0.125f) : 0.f;
            lsum0 += w00 + w01 + w10 + w11;
            lsum1 += w02 + w03 + w12 + w13;
            pfrag[kk][0] = packbf2(w00, w01);
            pfrag[kk][1] = packbf2(w02, w03);
            pfrag[kk][2] = packbf2(w10, w11);
            pfrag[kk][3] = packbf2(w12, w13);
        }

        for (int kk = 0; kk < 4; kk++) {
            for (int j = 0; j < 8; j++) {
                unsigned bb[2];
                unsigned a = smemu32(&Vs[kk * 16 + (lane & 15)][j * 8]);
                ldsm_x2t(bb[0], bb[1], a);
                mma_bf16(ctx[j], pfrag[kk], bb);
            }
        }
    }

    for (int o = 1; o < 4; o <<= 1) {
        lsum0 += __shfl_xor_sync(0xffffffffu, lsum0, o);
        lsum1 += __shfl_xor_sync(0xffffffffu, lsum1, o);
    }
    float inv0 = 1.f / lsum0;
    float inv1 = 1.f / lsum1;
    for (int j = 0; j < 8; j++) {
        int col = h * DHc + j * 8 + (lane & 3) * 2;
        if (row0 < qend) {
            unsigned p = packbf2(ctx[j][0] * inv0, ctx[j][1] * inv0);
            *(unsigned*)&g_CTXh[((size_t)(b * Tc + row0) * Dc) + col] = p;
        }
        if (row1 < qend) {
            unsigned p = packbf2(ctx[j][2] * inv1, ctx[j][3] * inv1);
            *(unsigned*)&g_CTXh[((size_t)(b * Tc + row1) * Dc) + col] = p;
        }
    }
}

// ---------------- SIMT attention (decode passes, len small) ----------------
__global__ void k_attn(int t0, int len) {
    __shared__ float Ks[64][64];
    __shared__ float Vs[64][64];
    int tid = threadIdx.x;
    int warp = tid >> 5;
    int lane = tid & 31;
    int tq = t0 + blockIdx.x * 8 + warp;
    int h = blockIdx.y;
    int b = blockIdx.z;
    bool valid = (tq < t0 + len);
    float qx = 0.f;
    float qy = 0.f;
    if (valid) {
        const float* qp = g_QKV + ((size_t)(b * Tc + tq) * 3 * Dc) + h * DHc;
        float2 q2 = ((const float2*)qp)[lane];
        qx = q2.x;
        qy = q2.y;
    }
    float l = 0.f;
    float a0 = 0.f;
    float a1 = 0.f;
    int tmaxb = t0 + (int)blockIdx.x * 8 + 7;
    if (tmaxb > t0 + len - 1) {
        tmaxb = t0 + len - 1;
    }
    for (int s0 = 0; s0 <= tmaxb; s0 += 64) {
        int rows = tmaxb + 1 - s0;
        if (rows > 64) {
            rows = 64;
        }
        for (int i = tid; i < rows * 16; i += 256) {
            int rr = i >> 4;
            int seg = i & 15;
            const float* base = g_QKV + ((size_t)(b * Tc + s0 + rr) * 3 * Dc) + Dc + h * DHc;
            ((float4*)&Ks[rr][0])[seg] = ((const float4*)base)[seg];
            ((float4*)&Vs[rr][0])[seg] = ((const float4*)(base + Dc))[seg];
        }
        __syncthreads();
        int send = 0;
        if (valid) {
            send = tq + 1 - s0;
            if (send > rows) {
                send = rows;
            }
        }
        for (int s = 0; s < send; s++) {
            float2 kv = ((const float2*)&Ks[s][0])[lane];
            float p = qx * kv.x + qy * kv.y;
            for (int o = 16; o > 0; o >>= 1) {
                p += __shfl_xor_sync(0xffffffffu, p, o);
            }
            float w = __expf(p * 0.125f);
            float2 vv = ((const float2*)&Vs[s][0])[lane];
            l += w;
            a0 += w * vv.x;
            a1 += w * vv.y;
        }
        __syncthreads();
    }
    if (valid) {
        float inv = 1.f / l;
        bf16* cp = g_CTXh + ((size_t)(b * Tc + tq) * Dc) + h * DHc;
        cp[lane * 2] = __float2bfloat16(a0 * inv);
        cp[lane * 2 + 1] = __float2bfloat16(a1 * inv);
    }
}

// ---------------- latent scatter ----------------
__global__ void k_latent(const float* __restrict__ latw, int tok, int n) {
    int b = blockIdx.y;
    int d = blockIdx.x * 256 + threadIdx.x;
    if (d >= Dc) {
        return;
    }
    float w[WINc];
    float mx = -1e30f;
    for (int i = 0; i < n; i++) {
        w[i] = latw[WINc - n + i];
        if (w[i] > mx) {
            mx = w[i];
        }
    }
    float ssum = 0.f;
    for (int i = 0; i < n; i++) {
        w[i] = expf(w[i] - mx);
        ssum += w[i];
    }
    float acc = 0.f;
    for (int i = 0; i < n; i++) {
        acc += (w[i] / ssum) * g_HID[(size_t)(b * Tc + tok - n + i) * Dc + d];
    }
    g_E[(size_t)(b * Tc + tok) * Dc + d] = acc;
}

// ---------------- lm_head fused with log-softmax partials (128 rows x 256 vocab) ----------------
__global__ __launch_bounds__(512, 1) void k_lmh(const int* __restrict__ labels) {
    __shared__ bf16 As[128][40];
    __shared__ bf16 Es[256][40];
    __shared__ float redM[128][8];
    __shared__ float redS[128][8];
    int tid = threadIdx.x;
    int lane = tid & 31;
    int warp = tid >> 5;
    int wy = warp >> 3;
    int wx = warp & 7;
    int vb = blockIdx.x * 256;
    int rb = blockIdx.y * 128;

    int arow = tid >> 2;
    int acol = (tid & 3) * 8;
    int erow = tid >> 1;
    int ecol = (tid & 1) * 16;
    const bf16* Aptr = g_HIDh + (size_t)(rb + arow) * Dc + acol;
    const bf16* Eptr = g_embh + (size_t)(vb + erow) * Dc + ecol;

    float acc[4][4][4];
    for (int i = 0; i < 4; i++) {
        for (int j = 0; j < 4; j++) {
            for (int r = 0; r < 4; r++) {
                acc[i][j][r] = 0.f;
            }
        }
    }

    uint4 av0 = *(const uint4*)(Aptr);
    uint4 ev0 = *(const uint4*)(Eptr);
    uint4 ev1 = *(const uint4*)(Eptr + 8);

    for (int k0 = 0; k0 < Dc; k0 += 32) {
        *(uint4*)&As[arow][acol] = av0;
        *(uint4*)&Es[erow][ecol] = ev0;
        *(uint4*)&Es[erow][ecol + 8] = ev1;
        __syncthreads();
        int kn = k0 + 32;
        if (kn < Dc) {
            av0 = *(const uint4*)(Aptr + kn);
            ev0 = *(const uint4*)(Eptr + kn);
            ev1 = *(const uint4*)(Eptr + kn + 8);
        }
        for (int kc = 0; kc < 32; kc += 16) {
            unsigned af[4][4];
            unsigned bfr[4][2];
            for (int i = 0; i < 4; i++) {
                unsigned a = smemu32(&As[wy * 64 + i * 16 + (lane & 15)][kc + 8 * (lane >> 4)]);
                ldsm_x4(af[i][0], af[i][1], af[i][2], af[i][3], a);
            }
            for (int j = 0; j < 4; j++) {
                unsigned a = smemu32(&Es[wx * 32 + j * 8 + (lane & 7)][kc + ((lane >> 3) & 1) * 8]);
                ldsm_x2(bfr[j][0], bfr[j][1], a);
            }
            for (int i = 0; i < 4; i++) {
                for (int j = 0; j < 4; j++) {
                    mma_bf16(acc[i][j], af[i], bfr[j]);
                }
            }
        }
        __syncthreads();
    }

    for (int i = 0; i < 4; i++) {
        for (int r2 = 0; r2 < 2; r2++) {
            int rowl = wy * 64 + i * 16 + (lane >> 2) + r2 * 8;
            int rid = rb + rowl;
            float m = -1e30f;
            for (int j = 0; j < 4; j++) {
                for (int c2 = 0; c2 < 2; c2++) {
                    float x = acc[i][j][r2 * 2 + c2];
                    if (x > m) {
                        m = x;
                    }
                }
            }
            float s = 0.f;
            for (int j = 0; j < 4; j++) {
                for (int c2 = 0; c2 < 2; c2++) {
                    s += __expf(acc[i][j][r2 * 2 + c2] - m);
                }
            }
            for (int o = 1; o < 4; o <<= 1) {
                float om = __shfl_xor_sync(0xffffffffu, m, o);
                float os = __shfl_xor_sync(0xffffffffu, s, o);
                float nm = fmaxf(m, om);
                s = s * __expf(m - nm) + os * __expf(om - nm);
                m = nm;
            }
            if ((lane & 3) == 0) {
                if (r2 == 0 && i >= 0) {
                    redM[rowl][wx] = m;
                    redS[rowl][wx] = s;
                } else {
                    redM[rowl][wx] = m;
                    redS[rowl][wx] = s;
                }
            }
            int t = rid & (Tc - 1);
            int b = rid >> 10;
            if (t < Tc - 1) {
                int lab = labels[b * Tc + t + 1];
                for (int j = 0; j < 4; j++) {
                    for (int c2 = 0; c2 < 2; c2++) {
                        int col = vb + wx * 32 + j * 8 + (lane & 3) * 2 + c2;
                        if (col == lab) {
                            g_labelLogit[rid] = acc[i][j][r2 * 2 + c2];
                        }
                    }
                }
            }
        }
    }
    __syncthreads();
    if (tid < 128) {
        float m = redM[tid][0];
        float s = redS[tid][0];
        for (int w2 = 1; w2 < 8; w2++) {
            float om = redM[tid][w2];
            float os = redS[tid][w2];
            float nm = fmaxf(m, om);
            s = s * __expf(m - nm) + os * __expf(om - nm);
            m = nm;
        }
        int rid = rb + tid;
        g_partM[(size_t)rid * VTc + blockIdx.x] = m;
        g_partS[(size_t)rid * VTc + blockIdx.x] = s;
    }
}

__global__ void k_lse(void) {
    __shared__ float sm[128];
    int row = blockIdx.x;
    int t = row & (Tc - 1);
    int tid = threadIdx.x;
    if (t == Tc - 1) {
        if (tid == 0) {
            g_nll[row] = 0.f;
        }
        return;
    }
    float M = -1e30f;
    for (int i = tid; i < VTc; i += 128) {
        float x = g_partM[(size_t)row * VTc + i];
        if (x > M) {
            M = x;
        }
    }
    sm[tid] = M;
    __syncthreads();
    for (int s = 64; s > 0; s >>= 1) {
        if (tid < s) {
            sm[tid] = fmaxf(sm[tid], sm[tid + s]);
        }
        __syncthreads();
    }
    M = sm[0];
    __syncthreads();
    float S = 0.f;
    for (int i = tid; i < VTc; i += 128) {
        S += g_partS[(size_t)row * VTc + i] * expf(g_partM[(size_t)row * VTc + i] - M);
    }
    sm[tid] = S;
    __syncthreads();
    for (int s = 64; s > 0; s >>= 1) {
        if (tid < s) {
            sm[tid] += sm[tid + s];
        }
        __syncthreads();
    }
    if (tid == 0) {
        g_nll[row] = M + logf(sm[0]) - g_labelLogit[row];
    }
}

__global__ void k_final(float* out) {
    __shared__ float sh[32];
    float s = 0.f;
    for (int i = threadIdx.x; i < NR; i += 256) {
        s += g_nll[i];
    }
    s = blockReduceSum(s, sh);
    if (threadIdx.x == 0) {
        out[0] = s / (float)(Bc * (Tc - 1));
    }
}

// ---------------- host orchestration ----------------
static void run_block(const bf16* pAh, const bf16* pWqkvH, const float* bqkv,
                      float* pQKV, bf16* pQKVh, const bf16* pCTXh, const bf16* pWoH,
                      const float* bo, float* pX, const float* ln2s, const float* ln2b,
                      const bf16* pW1H, const float* b1, bf16* pGh,
                      const bf16* pW2H, const float* b2,
                      const float* lnfs, const float* lnfb, bf16* pHIDh, float* pHID,
                      const float* Wpos, const float* ln1s, const float* ln1b,
                      int t0, int len)
{
    int M = 2 * len;
    int gy = (M + 127) / 128;
    k_ln1<<<M, 256>>>(Wpos, ln1s, ln1b, t0, len);
    k_gemm<<<dim3(3 * Dc / 128, gy), 256>>>(pAh, pWqkvH, bqkv, pQKV, pQKVh, t0, len, Dc, 3 * Dc, GF_BOTH);
    if (len >= 64) {
        k_flash<<<dim3((len + 63) / 64, Hc, Bc), 128>>>(t0, len);
    } else {
        k_attn<<<dim3((len + 7) / 8, Hc, Bc), 256>>>(t0, len);
    }
    k_gemm<<<dim3(Dc / 128, gy), 256>>>(pCTXh, pWoH, bo, pX, nullptr, t0, len, Dc, Dc, GF_ADD);
    k_lng<<<M, 256>>>(pX, ln2s, ln2b, (bf16*)pAh, nullptr, t0, len);
    k_gemm<<<dim3(DFFc / 128, gy), 256>>>(pAh, pW1H, b1, nullptr, pGh, t0, len, Dc, DFFc, GF_GELU | GF_STOREBF);
    k_gemm<<<dim3(Dc / 128, gy), 256>>>(pGh, pW2H, b2, pX, nullptr, t0, len, DFFc, Dc, GF_ADD);
    k_lng<<<M, 256>>>(pX, lnfs, lnfb, pHIDh, pHID, t0, len);
}

extern "C" void kernel_launch(void* const* d_in, const int* in_sizes, int n_in,
                              void* d_out, int out_size) {
    const int* ids = (const int*)d_in[0];
    const int* labels = (const int*)d_in[2];
    const float* emb = (const float*)d_in[4];
    const float* Wpos = (const float*)d_in[5];
    const float* Wqkv = (const float*)d_in[6];
    const float* bqkv = (const float*)d_in[7];
    const float* Aq = (const float*)d_in[8];
    const float* Bq = (const float*)d_in[9];
    const float* Wo = (const float*)d_in[10];
    const float* bo = (const float*)d_in[11];
    const float* Ao = (const float*)d_in[12];
    const float* Bo = (const float*)d_in[13];
    const float* W1 = (const float*)d_in[14];
    const float* b1 = (const float*)d_in[15];
    const float* W2 = (const float*)d_in[16];
    const float* b2 = (const float*)d_in[17];
    const float* ln1s = (const float*)d_in[18];
    const float* ln1b = (const float*)d_in[19];
    const float* ln2s = (const float*)d_in[20];
    const float* ln2b = (const float*)d_in[21];
    const float* lnfs = (const float*)d_in[22];
    const float* lnfb = (const float*)d_in[23];
    const float* latw = (const float*)d_in[24];

    void* vp = nullptr;
    cudaGetSymbolAddress(&vp, g_Wqkv_h);
    bf16* pWqkvH = (bf16*)vp;
    cudaGetSymbolAddress(&vp, g_Wo_h);
    bf16* pWoH = (bf16*)vp;
    cudaGetSymbolAddress(&vp, g_W1h);
    bf16* pW1H = (bf16*)vp;
    cudaGetSymbolAddress(&vp, g_W2h);
    bf16* pW2H = (bf16*)vp;
    cudaGetSymbolAddress(&vp, g_Ah);
    bf16* pAh = (bf16*)vp;
    cudaGetSymbolAddress(&vp, g_CTXh);
    bf16* pCTXh = (bf16*)vp;
    cudaGetSymbolAddress(&vp, g_Gh);
    bf16* pGh = (bf16*)vp;
    cudaGetSymbolAddress(&vp, g_HIDh);
    bf16* pHIDh = (bf16*)vp;
    cudaGetSymbolAddress(&vp, g_embh);
    bf16* pEmbH = (bf16*)vp;
    cudaGetSymbolAddress(&vp, g_X);
    float* pX = (float*)vp;
    cudaGetSymbolAddress(&vp, g_QKV);
    float* pQKV = (float*)vp;
    cudaGetSymbolAddress(&vp, g_QKVh);
    bf16* pQKVh = (bf16*)vp;
    cudaGetSymbolAddress(&vp, g_HID);
    float* pHID = (float*)vp;

    k_effqkv<<<(Dc * 3 * Dc + 255) / 256, 256>>>(Wqkv, Aq, Bq);
    k_effo<<<(Dc * Dc + 255) / 256, 256>>>(Wo, Ao, Bo);
    k_cvt<<<(Dc * DFFc / 4 + 255) / 256, 256>>>(W1, pW1H, Dc * DFFc);
    k_cvt<<<(DFFc * Dc / 4 + 255) / 256, 256>>>(W2, pW2H, DFFc * Dc);
    k_cvt<<<(Vc * Dc / 4 + 255) / 256, 256>>>(emb, pEmbH, Vc * Dc);
    k_embed<<<(NR * Dc + 255) / 256, 256>>>(ids, emb);

    run_block(pAh, pWqkvH, bqkv, pQKV, pQKVh, pCTXh, pWoH, bo, pX, ln2s, ln2b,
              pW1H, b1, pGh, pW2H, b2, lnfs, lnfb, pHIDh, pHID,
              Wpos, ln1s, ln1b, 0, 512);
    k_latent<<<dim3(4, Bc), 256>>>(latw, 512, 3);
    run_block(pAh, pWqkvH, bqkv, pQKV, pQKVh, pCTXh, pWoH, bo, pX, ln2s, ln2b,
              pW1H, b1, pGh, pW2H, b2, lnfs, lnfb, pHIDh, pHID,
              Wpos, ln1s, ln1b, 512, 1);
    k_latent<<<dim3(4, Bc), 256>>>(latw, 513, 1);
    run_block(pAh, pWqkvH, bqkv, pQKV, pQKVh, pCTXh, pWoH, bo, pX, ln2s, ln2b,
              pW1H, b1, pGh, pW2H, b2, lnfs, lnfb, pHIDh, pHID,
              Wpos, ln1s, ln1b, 513, 1);
    k_latent<<<dim3(4, Bc), 256>>>(latw, 514, 1);
    run_block(pAh, pWqkvH, bqkv, pQKV, pQKVh, pCTXh, pWoH, bo, pX, ln2s, ln2b,
              pW1H, b1, pGh, pW2H, b2, lnfs, lnfb, pHIDh, pHID,
              Wpos, ln1s, ln1b, 514, 1);
    k_latent<<<dim3(4, Bc), 256>>>(latw, 515, 1);
    run_block(pAh, pWqkvH, bqkv, pQKV, pQKVh, pCTXh, pWoH, bo, pX, ln2s, ln2b,
              pW1H, b1, pGh, pW2H, b2, lnfs, lnfb, pHIDh, pHID,
              Wpos, ln1s, ln1b, 515, 1);
    run_block(pAh, pWqkvH, bqkv, pQKV, pQKVh, pCTXh, pWoH, bo, pX, ln2s, ln2b,
              pW1H, b1, pGh, pW2H, b2, lnfs, lnfb, pHIDh, pHID,
              Wpos, ln1s, ln1b, 516, 508);

    k_lmh<<<dim3(VTc, NR / 128), 512>>>(labels);
    k_lse<<<NR, 128>>>();
    k_final<<<1, 256>>>((float*)d_out);
}